// round 13
// baseline (speedup 1.0000x reference)
#include <cuda_runtime.h>
#include <cuda_bf16.h>
#include <cuda_fp16.h>
#include <cstdint>
#include <math.h>

// ===========================================================================
// CrossAttention — R13: batch-split pipeline. KV runs as two half-launches
// (b 0-3, b 4-7); attention + out_e for the first half overlap KV's second
// half. Kernels and arithmetic identical to R12 (best 287.2 us, 3.62e-4).
// ===========================================================================

__device__ __forceinline__ uint32_t smem_u32(const void* p) {
    uint32_t a;
    asm("{ .reg .u64 t; cvta.to.shared.u64 t, %1; cvt.u32.u64 %0, t; }"
        : "=r"(a) : "l"(p));
    return a;
}

__device__ __forceinline__ void ldmx4t(uint32_t& r0, uint32_t& r1,
                                       uint32_t& r2, uint32_t& r3, uint32_t addr) {
    asm volatile("ldmatrix.sync.aligned.m8n8.x4.trans.shared.b16 {%0,%1,%2,%3}, [%4];"
                 : "=r"(r0), "=r"(r1), "=r"(r2), "=r"(r3) : "r"(addr));
}

__device__ __forceinline__ void mma_bf16(float* c, const uint32_t* a, const uint32_t* b) {
    asm volatile("mma.sync.aligned.m16n8k16.row.col.f32.bf16.bf16.f32 "
                 "{%0,%1,%2,%3}, {%4,%5,%6,%7}, {%8,%9}, {%0,%1,%2,%3};"
                 : "+f"(c[0]), "+f"(c[1]), "+f"(c[2]), "+f"(c[3])
                 : "r"(a[0]), "r"(a[1]), "r"(a[2]), "r"(a[3]),
                   "r"(b[0]), "r"(b[1]));
}

__device__ __forceinline__ void mma_f16(float* c, const uint32_t* a, const uint32_t* b) {
    asm volatile("mma.sync.aligned.m16n8k16.row.col.f32.f16.f16.f32 "
                 "{%0,%1,%2,%3}, {%4,%5,%6,%7}, {%8,%9}, {%0,%1,%2,%3};"
                 : "+f"(c[0]), "+f"(c[1]), "+f"(c[2]), "+f"(c[3])
                 : "r"(a[0]), "r"(a[1]), "r"(a[2]), "r"(a[3]),
                   "r"(b[0]), "r"(b[1]));
}

#define CP_ASYNC16(dst, src) \
    asm volatile("cp.async.cg.shared.global [%0], [%1], 16;" :: "r"(dst), "l"(src))
#define CP_COMMIT() asm volatile("cp.async.commit_group;" ::: "memory")
#define CP_WAIT0()  asm volatile("cp.async.wait_group 0;" ::: "memory")

// ---------------- scratch (device globals) ----------------------------------
__device__ float g_qe[16384ull * 256];
__device__ float g_oe[16384ull * 256];
__device__ __half g_koh[2048ull * 16384];
__device__ __half g_voh[2048ull * 16384];
__device__ float g_Co[256 * 256];
__device__ __align__(16) __half g_wkv[256 * 512];
__device__ __align__(16) unsigned short g_wq_h[65536], g_wq_l[65536];
__device__ __align__(16) unsigned short g_we_h[65536], g_we_l[65536];
__device__ __align__(16) unsigned short g_co_h[65536], g_co_l[65536];

// ---------------- C_o = Wv_ego @ W_out_other ---------------------------------
__global__ void __launch_bounds__(256)
compute_Co(const float* __restrict__ Wqkv_ego,
           const float* __restrict__ Wout_other,
           float* __restrict__ Co)
{
    const int c = blockIdx.x;
    const int o = threadIdx.x;
    const float* wv = Wqkv_ego + (size_t)c * 768 + 512;
    float a0 = 0.f, a1 = 0.f, a2 = 0.f, a3 = 0.f;
    #pragma unroll 4
    for (int m = 0; m < 256; m += 4) {
        a0 += wv[m + 0] * Wout_other[(m + 0) * 256 + o];
        a1 += wv[m + 1] * Wout_other[(m + 1) * 256 + o];
        a2 += wv[m + 2] * Wout_other[(m + 2) * 256 + o];
        a3 += wv[m + 3] * Wout_other[(m + 3) * 256 + o];
    }
    Co[c * 256 + o] = (a0 + a1) + (a2 + a3);
}

// ---------------- weight prep --------------------------------------------
__global__ void __launch_bounds__(256)
wsplit_kv(const float* __restrict__ Wqkv_o, __half* __restrict__ wkv)
{
    const int c = blockIdx.x, t = threadIdx.x;
    wkv[c * 512 + t]       = __float2half(Wqkv_o[(size_t)c * 768 + 256 + t]);
    wkv[c * 512 + 256 + t] = __float2half(Wqkv_o[(size_t)c * 768 + 512 + t]);
}

__device__ __forceinline__ void split1(float v, unsigned short* h, unsigned short* l) {
    const __nv_bfloat16 hh = __float2bfloat16(v);
    const __nv_bfloat16 ll = __float2bfloat16(v - __bfloat162float(hh));
    *h = __bfloat16_as_ushort(hh);
    *l = __bfloat16_as_ushort(ll);
}

__global__ void __launch_bounds__(256)
wsplit_rest(const float* __restrict__ Wqkv_e, const float* __restrict__ Wout_e,
            const float* __restrict__ Co,
            unsigned short* __restrict__ wq_h,  unsigned short* __restrict__ wq_l,
            unsigned short* __restrict__ we_h,  unsigned short* __restrict__ we_l,
            unsigned short* __restrict__ co_h,  unsigned short* __restrict__ co_l)
{
    const int c = blockIdx.x, t = threadIdx.x;
    split1(Wqkv_e[(size_t)c * 768 + t], wq_h + c * 256 + t, wq_l + c * 256 + t);
    split1(Wout_e[(size_t)c * 256 + t], we_h + c * 256 + t, we_l + c * 256 + t);
    split1(Co[(size_t)c * 256 + t],     co_h + c * 256 + t, co_l + c * 256 + t);
}

// =================== KV GEMM (identical core; goff selects batch half) ======
#define KV_A_BYTES 69632
#define KV_B_BUF   8704
#define KV_EPI_OFF 87040
#define KV_SMEM    103680

__global__ void __launch_bounds__(256, 2)
kv_gemm_f16(const float* __restrict__ A, const __half* __restrict__ Bw,
            __half* __restrict__ Ck, __half* __restrict__ Cv, int goff)
{
    extern __shared__ char smem[];
    const uint32_t sbase = smem_u32(smem);
    const int tid = threadIdx.x, lane = tid & 31, wid = tid >> 5;
    const int wm = wid & 1, wn = wid >> 1;
    const size_t g0 = (size_t)(goff + blockIdx.x) * 2;

    #pragma unroll
    for (int it = 0; it < 2; ++it) {
        const int s = tid + (it << 8);
        const int row = s >> 4, seg = s & 15;
        CP_ASYNC16(sbase + KV_A_BYTES + row * 272 + seg * 16,
                   Bw + (size_t)row * 512 + seg * 8);
    }
    CP_COMMIT();

    {
        const int sm = (tid & 31) * 4;
        const int sk = tid >> 5;
        const float* Abase = A + (g0 + (size_t)(sm >> 6)) * 16384 + (sm & 63);
        #pragma unroll 4
        for (int k = sk; k < 256; k += 8) {
            const float4 v = *(const float4*)(Abase + (size_t)k * 64);
            char* ph = smem + (size_t)k * 272 + sm * 2;
            *(__half2*)(ph)     = __floats2half2_rn(v.x, v.y);
            *(__half2*)(ph + 4) = __floats2half2_rn(v.z, v.w);
        }
    }
    CP_WAIT0();
    __syncthreads();

    const int a_k = (lane & 7) + ((lane >> 4) << 3);
    const int a_m = ((lane >> 3) & 1) << 3;
    const int b_k = (lane & 7) + (((lane >> 3) & 1) << 3);
    const int b_n = (lane >> 4) << 3;
    const int r0 = lane >> 2;
    const int c2 = (lane & 3) * 2;

    int buf = 0;
    #pragma unroll 1
    for (int nc = 0; nc < 4; ++nc) {
        const int col0 = nc * 128;

        float acc[4][4][4];
        #pragma unroll
        for (int i = 0; i < 4; ++i)
            #pragma unroll
            for (int j = 0; j < 4; ++j)
                #pragma unroll
                for (int r = 0; r < 4; ++r) acc[i][j][r] = 0.f;

        #pragma unroll 1
        for (int ch = 0; ch < 8; ++ch) {
            {
                int pnc = nc, pch = ch + 1;
                if (pch == 8) { pnc = nc + 1; pch = 0; }
                if (pnc < 4) {
                    const uint32_t nb = sbase + KV_A_BYTES + (buf ^ 1) * KV_B_BUF;
                    const int pc0 = pch << 5;
                    const int pcol0 = pnc * 128;
                    #pragma unroll
                    for (int it = 0; it < 2; ++it) {
                        const int s = tid + (it << 8);
                        const int row = s >> 4, seg = s & 15;
                        CP_ASYNC16(nb + row * 272 + seg * 16,
                                   Bw + (size_t)(pc0 + row) * 512 + pcol0 + seg * 8);
                    }
                    CP_COMMIT();
                }
            }

            {
                const uint32_t Bb = sbase + KV_A_BYTES + buf * KV_B_BUF;
                #pragma unroll
                for (int s = 0; s < 2; ++s) {
                    const int klo = s << 4;
                    const int ak = ch * 32 + klo + a_k;
                    uint32_t bh[4][2], ah[4][4];
                    #pragma unroll
                    for (int nbj = 0; nbj < 2; ++nbj)
                        ldmx4t(bh[2 * nbj][0], bh[2 * nbj][1],
                               bh[2 * nbj + 1][0], bh[2 * nbj + 1][1],
                               Bb + ((klo + b_k) * 136 + wn * 32 + nbj * 16 + b_n) * 2);
                    #pragma unroll
                    for (int mi = 0; mi < 4; ++mi)
                        ldmx4t(ah[mi][0], ah[mi][1], ah[mi][2], ah[mi][3],
                               sbase + (ak * 136 + wm * 64 + mi * 16 + a_m) * 2);
                    #pragma unroll
                    for (int mi = 0; mi < 4; ++mi)
                        #pragma unroll
                        for (int nj = 0; nj < 4; ++nj)
                            mma_f16(acc[mi][nj], ah[mi], bh[nj]);
                }
            }

            CP_WAIT0();
            __syncthreads();
            buf ^= 1;
        }

        __half* arr = (col0 < 256) ? Ck : Cv;
        const int c0 = col0 & 255;
        char* es = smem + KV_EPI_OFF;
        #pragma unroll 1
        for (int p = 0; p < 2; ++p) {
            if (wm == p) {
                #pragma unroll
                for (int mi = 0; mi < 4; ++mi) {
                    const int px = mi * 16 + r0;
                    #pragma unroll
                    for (int nj = 0; nj < 4; ++nj) {
                        const int col = wn * 32 + nj * 8 + c2;
                        *(__half2*)(es + (size_t)px * 260 + col * 2) =
                            __floats2half2_rn(acc[mi][nj][0], acc[mi][nj][1]);
                        *(__half2*)(es + (size_t)(px + 8) * 260 + col * 2) =
                            __floats2half2_rn(acc[mi][nj][2], acc[mi][nj][3]);
                    }
                }
            }
            __syncthreads();
            #pragma unroll
            for (int it = 0; it < 4; ++it) {
                const int cid = tid + (it << 8);
                const int col = cid >> 3;
                const int v8  = cid & 7;
                union { __half h[8]; uint4 u; } pk;
                #pragma unroll
                for (int pp = 0; pp < 8; ++pp)
                    pk.h[pp] = *(__half*)(es + (size_t)(v8 * 8 + pp) * 260 + col * 2);
                *(uint4*)(arr + (g0 + p) * 16384 + (size_t)(c0 + col) * 64 + v8 * 8) = pk.u;
            }
            __syncthreads();
        }
    }
}

// =================== bf16-split GEMM (modes 0/1; yoff for row-half) =========
#define BUF_BYTES 34816
#define GEMM_SMEM (2 * BUF_BYTES)

template <int MODE>
__global__ void __launch_bounds__(256, 2)
bf16_gemm(const float* __restrict__ A,
          const unsigned short* __restrict__ Bh,
          const unsigned short* __restrict__ Bl, int ldb,
          float* __restrict__ C,
          const float* __restrict__ bias, int yoff)
{
    extern __shared__ char smem[];
    const uint32_t sbase = smem_u32(smem);
    const int tid = threadIdx.x, lane = tid & 31, wid = tid >> 5;
    const int wm = wid & 1, wn = wid >> 1;
    const size_t g0 = (size_t)(blockIdx.y + yoff) * 2;
    const int bcol0 = blockIdx.x * 128;

    const int sm = (tid & 31) * 4;
    const int sk = tid >> 5;
    const float* Abase = A + (g0 + (size_t)(sm >> 6)) * 16384 + (sm & 63);

    const int a_k = (lane & 7) + ((lane >> 4) << 3);
    const int a_m = ((lane >> 3) & 1) << 3;
    const int b_k = (lane & 7) + (((lane >> 3) & 1) << 3);
    const int b_n = (lane >> 4) << 3;

    float acc[4][4][4];
    #pragma unroll
    for (int i = 0; i < 4; ++i)
        #pragma unroll
        for (int j = 0; j < 4; ++j)
            #pragma unroll
            for (int r = 0; r < 4; ++r) acc[i][j][r] = 0.f;

    float4 areg[4];

    #pragma unroll
    for (int it = 0; it < 4; ++it)
        areg[it] = *(const float4*)(Abase + (size_t)(sk + it * 8) * 64);
    #pragma unroll
    for (int it = 0; it < 4; ++it) {
        const int s = tid + (it << 8);
        const int sel = s >> 9, row = (s >> 4) & 31, seg = s & 15;
        const unsigned short* src = (sel ? Bl : Bh)
            + (size_t)row * ldb + bcol0 + seg * 8;
        CP_ASYNC16(sbase + 17408 + sel * 8704 + row * 272 + seg * 16, src);
    }
    CP_COMMIT();
    #pragma unroll
    for (int it = 0; it < 4; ++it) {
        const int k = sk + it * 8;
        const float4 v = areg[it];
        __nv_bfloat162 h01 = __floats2bfloat162_rn(v.x, v.y);
        __nv_bfloat162 h23 = __floats2bfloat162_rn(v.z, v.w);
        float2 f01 = __bfloat1622float2(h01);
        float2 f23 = __bfloat1622float2(h23);
        __nv_bfloat162 l01 = __floats2bfloat162_rn(v.x - f01.x, v.y - f01.y);
        __nv_bfloat162 l23 = __floats2bfloat162_rn(v.z - f23.x, v.w - f23.y);
        char* ph = smem + (size_t)k * 272 + sm * 2;
        *(__nv_bfloat162*)(ph)     = h01;
        *(__nv_bfloat162*)(ph + 4) = h23;
        char* pl = ph + 8704;
        *(__nv_bfloat162*)(pl)     = l01;
        *(__nv_bfloat162*)(pl + 4) = l23;
    }
    CP_WAIT0();
    __syncthreads();

    int buf = 0;
    #pragma unroll 1
    for (int ch = 0; ch < 8; ++ch) {
        const int nc0 = (ch + 1) << 5;
        if (ch < 7) {
            #pragma unroll
            for (int it = 0; it < 4; ++it)
                areg[it] = *(const float4*)(Abase + (size_t)(nc0 + sk + it * 8) * 64);
            const uint32_t nb = sbase + (buf ^ 1) * BUF_BYTES;
            #pragma unroll
            for (int it = 0; it < 4; ++it) {
                const int s = tid + (it << 8);
                const int sel = s >> 9, row = (s >> 4) & 31, seg = s & 15;
                const unsigned short* src = (sel ? Bl : Bh)
                    + (size_t)(nc0 + row) * ldb + bcol0 + seg * 8;
                CP_ASYNC16(nb + 17408 + sel * 8704 + row * 272 + seg * 16, src);
            }
            CP_COMMIT();
        }

        {
            const uint32_t Ab = sbase + buf * BUF_BYTES;
            const uint32_t Bb = Ab + 17408;
            #pragma unroll
            for (int s = 0; s < 2; ++s) {
                const int klo = s << 4;
                uint32_t bh[4][2], ah[4][4];
                #pragma unroll
                for (int nbj = 0; nbj < 2; ++nbj)
                    ldmx4t(bh[2 * nbj][0], bh[2 * nbj][1],
                           bh[2 * nbj + 1][0], bh[2 * nbj + 1][1],
                           Bb + ((klo + b_k) * 136 + wn * 32 + nbj * 16 + b_n) * 2);
                #pragma unroll
                for (int mi = 0; mi < 4; ++mi)
                    ldmx4t(ah[mi][0], ah[mi][1], ah[mi][2], ah[mi][3],
                           Ab + ((klo + a_k) * 136 + wm * 64 + mi * 16 + a_m) * 2);
                #pragma unroll
                for (int mi = 0; mi < 4; ++mi)
                    #pragma unroll
                    for (int nj = 0; nj < 4; ++nj)
                        mma_bf16(acc[mi][nj], ah[mi], bh[nj]);
                {
                    uint32_t al[4][4];
                    #pragma unroll
                    for (int mi = 0; mi < 4; ++mi)
                        ldmx4t(al[mi][0], al[mi][1], al[mi][2], al[mi][3],
                               Ab + 8704 + ((klo + a_k) * 136 + wm * 64 + mi * 16 + a_m) * 2);
                    #pragma unroll
                    for (int mi = 0; mi < 4; ++mi)
                        #pragma unroll
                        for (int nj = 0; nj < 4; ++nj)
                            mma_bf16(acc[mi][nj], al[mi], bh[nj]);
                }
                {
                    uint32_t bl[4][2];
                    #pragma unroll
                    for (int nbj = 0; nbj < 2; ++nbj)
                        ldmx4t(bl[2 * nbj][0], bl[2 * nbj][1],
                               bl[2 * nbj + 1][0], bl[2 * nbj + 1][1],
                               Bb + 8704 + ((klo + b_k) * 136 + wn * 32 + nbj * 16 + b_n) * 2);
                    #pragma unroll
                    for (int mi = 0; mi < 4; ++mi)
                        #pragma unroll
                        for (int nj = 0; nj < 4; ++nj)
                            mma_bf16(acc[mi][nj], ah[mi], bl[nj]);
                }
            }
        }

        if (ch < 7) {
            char* nbuf = smem + (buf ^ 1) * BUF_BYTES;
            #pragma unroll
            for (int it = 0; it < 4; ++it) {
                const int k = sk + it * 8;
                const float4 v = areg[it];
                __nv_bfloat162 h01 = __floats2bfloat162_rn(v.x, v.y);
                __nv_bfloat162 h23 = __floats2bfloat162_rn(v.z, v.w);
                float2 f01 = __bfloat1622float2(h01);
                float2 f23 = __bfloat1622float2(h23);
                __nv_bfloat162 l01 = __floats2bfloat162_rn(v.x - f01.x, v.y - f01.y);
                __nv_bfloat162 l23 = __floats2bfloat162_rn(v.z - f23.x, v.w - f23.y);
                char* ph = nbuf + (size_t)k * 272 + sm * 2;
                *(__nv_bfloat162*)(ph)     = h01;
                *(__nv_bfloat162*)(ph + 4) = h23;
                char* pl = ph + 8704;
                *(__nv_bfloat162*)(pl)     = l01;
                *(__nv_bfloat162*)(pl + 4) = l23;
            }
        }
        CP_WAIT0();
        __syncthreads();
        buf ^= 1;
    }

    const int r0 = lane >> 2;
    const int c2 = (lane & 3) * 2;
    #pragma unroll
    for (int mi = 0; mi < 4; ++mi) {
        const int mA = wm * 64 + mi * 16 + r0;
        const size_t gg = g0 + (size_t)(mA >> 6);
        const int n = mA & 63;
        #pragma unroll
        for (int nj = 0; nj < 4; ++nj) {
            const int col = bcol0 + wn * 32 + nj * 8 + c2;
            const float b0 = bias ? __ldg(bias + col)     : 0.f;
            const float b1 = bias ? __ldg(bias + col + 1) : 0.f;
            const float v00 = acc[mi][nj][0] + b0;
            const float v01 = acc[mi][nj][1] + b1;
            const float v10 = acc[mi][nj][2] + b0;
            const float v11 = acc[mi][nj][3] + b1;
            if (MODE == 0) {
                float* p = C + gg * 16384 + (size_t)col * 64 + n;
                p[0]      = v00;
                p[64]     = v01;
                p[8]      = v10;
                p[64 + 8] = v11;
            } else {
                const size_t dg0 = (gg >> 5) * 256 + (gg & 31);
                #pragma unroll
                for (int l = 0; l < 8; ++l) {
                    float* p = C + (dg0 + (size_t)l * 32) * 16384 + (size_t)col * 64 + n;
                    p[0]      = v00;
                    p[64]     = v01;
                    p[8]      = v10;
                    p[64 + 8] = v11;
                }
            }
        }
    }
}

// ---------------- attention (boff selects batch half) ------------------------
__global__ void __launch_bounds__(256)
attn_kernel(const float* __restrict__ qe, const __half* __restrict__ ko,
            const __half* __restrict__ vo, float* __restrict__ oe, int boff)
{
    const int bx = blockIdx.x + boff;
    const int ge = bx >> 1;                      // b*32 + k
    const int b  = ge >> 5;
    const int k  = ge & 31;
    const int h  = ((bx & 1) << 2) + (threadIdx.x >> 6);
    const int n  = threadIdx.x & 63;
    const float scale = 0.1767766952966369f;     // 32^-0.5

    const float* qp = qe + ((size_t)ge * 256 + h * 32) * 64 + n;
    float q[32];
    #pragma unroll
    for (int d = 0; d < 32; ++d) q[d] = qp[d * 64];

    float logit[8];
    #pragma unroll
    for (int j = 0; j < 8; ++j) {
        const size_t go = (size_t)(b * 8 + j) * 32 + k;
        const __half* kp = ko + (go * 256 + h * 32) * 64 + n;
        float s = 0.f;
        #pragma unroll
        for (int d = 0; d < 32; ++d) s += q[d] * __half2float(kp[d * 64]);
        logit[j] = s * scale;
    }

    float m = logit[0];
    #pragma unroll
    for (int j = 1; j < 8; ++j) m = fmaxf(m, logit[j]);
    float denom = 0.f;
    #pragma unroll
    for (int j = 0; j < 8; ++j) { logit[j] = expf(logit[j] - m); denom += logit[j]; }
    const float inv = 1.f / denom;

    float o[32];
    #pragma unroll
    for (int d = 0; d < 32; ++d) o[d] = 0.f;
    #pragma unroll
    for (int j = 0; j < 8; ++j) {
        const float a = logit[j] * inv;
        const __half* vp = vo + ((size_t)(b * 8 + j) * 32 + k) * 16384 + (h * 32) * 64 + n;
        #pragma unroll
        for (int d = 0; d < 32; ++d) o[d] += a * __half2float(vp[d * 64]);
    }

    float* op = oe + ((size_t)ge * 256 + h * 32) * 64 + n;
    #pragma unroll
    for (int d = 0; d < 32; ++d) op[d * 64] = o[d];
}

// ---------------- launcher ---------------------------------------------------
extern "C" void kernel_launch(void* const* d_in, const int* in_sizes, int n_in,
                              void* d_out, int out_size)
{
    const float* ego    = (const float*)d_in[0];
    const float* oth    = (const float*)d_in[1];
    const float* Wqkv_e = (const float*)d_in[2];
    const float* Wqkv_o = (const float*)d_in[3];
    const float* Wout_e = (const float*)d_in[4];
    const float* bout_e = (const float*)d_in[5];
    const float* Wout_o = (const float*)d_in[6];
    const float* bout_o = (const float*)d_in[7];

    float* outE = (float*)d_out;
    float* outO = outE + 16384ull * 256;

    float *qe, *oe, *Co;
    __half *koh, *voh, *wkv;
    unsigned short *wq_h, *wq_l, *we_h, *we_l, *co_h, *co_l;
    cudaGetSymbolAddress((void**)&qe, g_qe);
    cudaGetSymbolAddress((void**)&oe, g_oe);
    cudaGetSymbolAddress((void**)&koh, g_koh);
    cudaGetSymbolAddress((void**)&voh, g_voh);
    cudaGetSymbolAddress((void**)&Co, g_Co);
    cudaGetSymbolAddress((void**)&wkv, g_wkv);
    cudaGetSymbolAddress((void**)&wq_h, g_wq_h); cudaGetSymbolAddress((void**)&wq_l, g_wq_l);
    cudaGetSymbolAddress((void**)&we_h, g_we_h); cudaGetSymbolAddress((void**)&we_l, g_we_l);
    cudaGetSymbolAddress((void**)&co_h, g_co_h); cudaGetSymbolAddress((void**)&co_l, g_co_l);

    static cudaStream_t sKV = nullptr;
    static cudaEvent_t evW = nullptr, evK1 = nullptr, evK2 = nullptr;
    if (!sKV) {
        cudaStreamCreateWithFlags(&sKV, cudaStreamNonBlocking);
        cudaEventCreateWithFlags(&evW, cudaEventDisableTiming);
        cudaEventCreateWithFlags(&evK1, cudaEventDisableTiming);
        cudaEventCreateWithFlags(&evK2, cudaEventDisableTiming);
        cudaFuncSetAttribute(bf16_gemm<0>, cudaFuncAttributeMaxDynamicSharedMemorySize, GEMM_SMEM);
        cudaFuncSetAttribute(bf16_gemm<1>, cudaFuncAttributeMaxDynamicSharedMemorySize, GEMM_SMEM);
        cudaFuncSetAttribute(kv_gemm_f16, cudaFuncAttributeMaxDynamicSharedMemorySize, KV_SMEM);
    }

    // ---- KV-critical weight prep first, then fork KV halves on side stream
    wsplit_kv<<<256, 256>>>(Wqkv_o, wkv);
    cudaEventRecord(evW, 0);
    cudaStreamWaitEvent(sKV, evW, 0);
    kv_gemm_f16<<<512, 256, KV_SMEM, sKV>>>(oth, wkv, koh, voh, 0);    // b 0-3
    cudaEventRecord(evK1, sKV);
    kv_gemm_f16<<<512, 256, KV_SMEM, sKV>>>(oth, wkv, koh, voh, 512);  // b 4-7
    cudaEventRecord(evK2, sKV);

    // ---- remaining weight prep + small GEMMs on default stream (overlap KV1)
    compute_Co<<<256, 256>>>(Wqkv_e, Wout_o, Co);
    wsplit_rest<<<256, 256>>>(Wqkv_e, Wout_e, Co,
                              wq_h, wq_l, we_h, we_l, co_h, co_l);
    bf16_gemm<0><<<dim3(2, 128), 256, GEMM_SMEM>>>(
        ego, wq_h, wq_l, 256, qe, nullptr, 0);
    bf16_gemm<1><<<dim3(2, 128), 256, GEMM_SMEM>>>(
        ego, co_h, co_l, 256, outO, bout_o, 0);

    // ---- half 1: attn + out_e for b 0-3 (overlaps KV half 2)
    cudaStreamWaitEvent(0, evK1, 0);
    attn_kernel<<<256, 256>>>(qe, koh, voh, oe, 0);
    bf16_gemm<0><<<dim3(2, 64), 256, GEMM_SMEM>>>(
        oe, we_h, we_l, 256, outE, bout_e, 0);

    // ---- half 2: attn + out_e for b 4-7
    cudaStreamWaitEvent(0, evK2, 0);
    attn_kernel<<<256, 256>>>(qe, koh, voh, oe, 256);
    bf16_gemm<0><<<dim3(2, 64), 256, GEMM_SMEM>>>(
        oe, we_h, we_l, 256, outE, bout_e, 64);
}

// round 14
// speedup vs baseline: 1.2209x; 1.2209x over previous
#include <cuda_runtime.h>
#include <cuda_bf16.h>
#include <cuda_fp16.h>
#include <cstdint>
#include <math.h>

// ===========================================================================
// CrossAttention — R14: R12 structure (best config) + non-volatile MMA asm
// (ldsm stays volatile) so the compiler can interleave ldsm latency with
// tensor work in all GEMM hot loops. Arithmetic identical (rel_err 3.62e-4).
// ===========================================================================

__device__ __forceinline__ uint32_t smem_u32(const void* p) {
    uint32_t a;
    asm("{ .reg .u64 t; cvta.to.shared.u64 t, %1; cvt.u32.u64 %0, t; }"
        : "=r"(a) : "l"(p));
    return a;
}

// volatile: must stay ordered w.r.t. cp.async.wait / __syncthreads
__device__ __forceinline__ void ldmx4t(uint32_t& r0, uint32_t& r1,
                                       uint32_t& r2, uint32_t& r3, uint32_t addr) {
    asm volatile("ldmatrix.sync.aligned.m8n8.x4.trans.shared.b16 {%0,%1,%2,%3}, [%4];"
                 : "=r"(r0), "=r"(r1), "=r"(r2), "=r"(r3) : "r"(addr));
}

// NON-volatile: register-only; lets the scheduler interleave with ldsm
__device__ __forceinline__ void mma_bf16(float* c, const uint32_t* a, const uint32_t* b) {
    asm("mma.sync.aligned.m16n8k16.row.col.f32.bf16.bf16.f32 "
        "{%0,%1,%2,%3}, {%4,%5,%6,%7}, {%8,%9}, {%0,%1,%2,%3};"
        : "+f"(c[0]), "+f"(c[1]), "+f"(c[2]), "+f"(c[3])
        : "r"(a[0]), "r"(a[1]), "r"(a[2]), "r"(a[3]),
          "r"(b[0]), "r"(b[1]));
}

__device__ __forceinline__ void mma_f16(float* c, const uint32_t* a, const uint32_t* b) {
    asm("mma.sync.aligned.m16n8k16.row.col.f32.f16.f16.f32 "
        "{%0,%1,%2,%3}, {%4,%5,%6,%7}, {%8,%9}, {%0,%1,%2,%3};"
        : "+f"(c[0]), "+f"(c[1]), "+f"(c[2]), "+f"(c[3])
        : "r"(a[0]), "r"(a[1]), "r"(a[2]), "r"(a[3]),
          "r"(b[0]), "r"(b[1]));
}

#define CP_ASYNC16(dst, src) \
    asm volatile("cp.async.cg.shared.global [%0], [%1], 16;" :: "r"(dst), "l"(src))
#define CP_COMMIT() asm volatile("cp.async.commit_group;" ::: "memory")
#define CP_WAIT0()  asm volatile("cp.async.wait_group 0;" ::: "memory")

// ---------------- scratch (device globals) ----------------------------------
__device__ float g_qe[16384ull * 256];
__device__ float g_oe[16384ull * 256];
__device__ __half g_koh[2048ull * 16384];
__device__ __half g_voh[2048ull * 16384];
__device__ float g_Co[256 * 256];
__device__ __align__(16) __half g_wkv[256 * 512];
__device__ __align__(16) unsigned short g_wq_h[65536], g_wq_l[65536];
__device__ __align__(16) unsigned short g_we_h[65536], g_we_l[65536];
__device__ __align__(16) unsigned short g_co_h[65536], g_co_l[65536];

// ---------------- C_o = Wv_ego @ W_out_other ---------------------------------
__global__ void __launch_bounds__(256)
compute_Co(const float* __restrict__ Wqkv_ego,
           const float* __restrict__ Wout_other,
           float* __restrict__ Co)
{
    const int c = blockIdx.x;
    const int o = threadIdx.x;
    const float* wv = Wqkv_ego + (size_t)c * 768 + 512;
    float a0 = 0.f, a1 = 0.f, a2 = 0.f, a3 = 0.f;
    #pragma unroll 4
    for (int m = 0; m < 256; m += 4) {
        a0 += wv[m + 0] * Wout_other[(m + 0) * 256 + o];
        a1 += wv[m + 1] * Wout_other[(m + 1) * 256 + o];
        a2 += wv[m + 2] * Wout_other[(m + 2) * 256 + o];
        a3 += wv[m + 3] * Wout_other[(m + 3) * 256 + o];
    }
    Co[c * 256 + o] = (a0 + a1) + (a2 + a3);
}

// ---------------- weight prep --------------------------------------------
__global__ void __launch_bounds__(256)
wsplit_kv(const float* __restrict__ Wqkv_o, __half* __restrict__ wkv)
{
    const int c = blockIdx.x, t = threadIdx.x;
    wkv[c * 512 + t]       = __float2half(Wqkv_o[(size_t)c * 768 + 256 + t]);
    wkv[c * 512 + 256 + t] = __float2half(Wqkv_o[(size_t)c * 768 + 512 + t]);
}

__device__ __forceinline__ void split1(float v, unsigned short* h, unsigned short* l) {
    const __nv_bfloat16 hh = __float2bfloat16(v);
    const __nv_bfloat16 ll = __float2bfloat16(v - __bfloat162float(hh));
    *h = __bfloat16_as_ushort(hh);
    *l = __bfloat16_as_ushort(ll);
}

__global__ void __launch_bounds__(256)
wsplit_rest(const float* __restrict__ Wqkv_e, const float* __restrict__ Wout_e,
            const float* __restrict__ Co,
            unsigned short* __restrict__ wq_h,  unsigned short* __restrict__ wq_l,
            unsigned short* __restrict__ we_h,  unsigned short* __restrict__ we_l,
            unsigned short* __restrict__ co_h,  unsigned short* __restrict__ co_l)
{
    const int c = blockIdx.x, t = threadIdx.x;
    split1(Wqkv_e[(size_t)c * 768 + t], wq_h + c * 256 + t, wq_l + c * 256 + t);
    split1(Wout_e[(size_t)c * 256 + t], we_h + c * 256 + t, we_l + c * 256 + t);
    split1(Co[(size_t)c * 256 + t],     co_h + c * 256 + t, co_l + c * 256 + t);
}

// =================== KV GEMM: persistent fp16 A, pipelined B ================
#define KV_A_BYTES 69632
#define KV_B_BUF   8704
#define KV_EPI_OFF 87040
#define KV_SMEM    103680

__global__ void __launch_bounds__(256, 2)
kv_gemm_f16(const float* __restrict__ A, const __half* __restrict__ Bw,
            __half* __restrict__ Ck, __half* __restrict__ Cv)
{
    extern __shared__ char smem[];
    const uint32_t sbase = smem_u32(smem);
    const int tid = threadIdx.x, lane = tid & 31, wid = tid >> 5;
    const int wm = wid & 1, wn = wid >> 1;
    const size_t g0 = (size_t)blockIdx.x * 2;

    #pragma unroll
    for (int it = 0; it < 2; ++it) {
        const int s = tid + (it << 8);
        const int row = s >> 4, seg = s & 15;
        CP_ASYNC16(sbase + KV_A_BYTES + row * 272 + seg * 16,
                   Bw + (size_t)row * 512 + seg * 8);
    }
    CP_COMMIT();

    {
        const int sm = (tid & 31) * 4;
        const int sk = tid >> 5;
        const float* Abase = A + (g0 + (size_t)(sm >> 6)) * 16384 + (sm & 63);
        #pragma unroll 4
        for (int k = sk; k < 256; k += 8) {
            const float4 v = *(const float4*)(Abase + (size_t)k * 64);
            char* ph = smem + (size_t)k * 272 + sm * 2;
            *(__half2*)(ph)     = __floats2half2_rn(v.x, v.y);
            *(__half2*)(ph + 4) = __floats2half2_rn(v.z, v.w);
        }
    }
    CP_WAIT0();
    __syncthreads();

    const int a_k = (lane & 7) + ((lane >> 4) << 3);
    const int a_m = ((lane >> 3) & 1) << 3;
    const int b_k = (lane & 7) + (((lane >> 3) & 1) << 3);
    const int b_n = (lane >> 4) << 3;
    const int r0 = lane >> 2;
    const int c2 = (lane & 3) * 2;

    int buf = 0;
    #pragma unroll 1
    for (int nc = 0; nc < 4; ++nc) {
        const int col0 = nc * 128;

        float acc[4][4][4];
        #pragma unroll
        for (int i = 0; i < 4; ++i)
            #pragma unroll
            for (int j = 0; j < 4; ++j)
                #pragma unroll
                for (int r = 0; r < 4; ++r) acc[i][j][r] = 0.f;

        #pragma unroll 1
        for (int ch = 0; ch < 8; ++ch) {
            {
                int pnc = nc, pch = ch + 1;
                if (pch == 8) { pnc = nc + 1; pch = 0; }
                if (pnc < 4) {
                    const uint32_t nb = sbase + KV_A_BYTES + (buf ^ 1) * KV_B_BUF;
                    const int pc0 = pch << 5;
                    const int pcol0 = pnc * 128;
                    #pragma unroll
                    for (int it = 0; it < 2; ++it) {
                        const int s = tid + (it << 8);
                        const int row = s >> 4, seg = s & 15;
                        CP_ASYNC16(nb + row * 272 + seg * 16,
                                   Bw + (size_t)(pc0 + row) * 512 + pcol0 + seg * 8);
                    }
                    CP_COMMIT();
                }
            }

            {
                const uint32_t Bb = sbase + KV_A_BYTES + buf * KV_B_BUF;
                #pragma unroll
                for (int s = 0; s < 2; ++s) {
                    const int klo = s << 4;
                    const int ak = ch * 32 + klo + a_k;
                    uint32_t bh[4][2], ah[4][4];
                    #pragma unroll
                    for (int nbj = 0; nbj < 2; ++nbj)
                        ldmx4t(bh[2 * nbj][0], bh[2 * nbj][1],
                               bh[2 * nbj + 1][0], bh[2 * nbj + 1][1],
                               Bb + ((klo + b_k) * 136 + wn * 32 + nbj * 16 + b_n) * 2);
                    #pragma unroll
                    for (int mi = 0; mi < 4; ++mi)
                        ldmx4t(ah[mi][0], ah[mi][1], ah[mi][2], ah[mi][3],
                               sbase + (ak * 136 + wm * 64 + mi * 16 + a_m) * 2);
                    #pragma unroll
                    for (int mi = 0; mi < 4; ++mi)
                        #pragma unroll
                        for (int nj = 0; nj < 4; ++nj)
                            mma_f16(acc[mi][nj], ah[mi], bh[nj]);
                }
            }

            CP_WAIT0();
            __syncthreads();
            buf ^= 1;
        }

        __half* arr = (col0 < 256) ? Ck : Cv;
        const int c0 = col0 & 255;
        char* es = smem + KV_EPI_OFF;
        #pragma unroll 1
        for (int p = 0; p < 2; ++p) {
            if (wm == p) {
                #pragma unroll
                for (int mi = 0; mi < 4; ++mi) {
                    const int px = mi * 16 + r0;
                    #pragma unroll
                    for (int nj = 0; nj < 4; ++nj) {
                        const int col = wn * 32 + nj * 8 + c2;
                        *(__half2*)(es + (size_t)px * 260 + col * 2) =
                            __floats2half2_rn(acc[mi][nj][0], acc[mi][nj][1]);
                        *(__half2*)(es + (size_t)(px + 8) * 260 + col * 2) =
                            __floats2half2_rn(acc[mi][nj][2], acc[mi][nj][3]);
                    }
                }
            }
            __syncthreads();
            #pragma unroll
            for (int it = 0; it < 4; ++it) {
                const int cid = tid + (it << 8);
                const int col = cid >> 3;
                const int v8  = cid & 7;
                union { __half h[8]; uint4 u; } pk;
                #pragma unroll
                for (int pp = 0; pp < 8; ++pp)
                    pk.h[pp] = *(__half*)(es + (size_t)(v8 * 8 + pp) * 260 + col * 2);
                *(uint4*)(arr + (g0 + p) * 16384 + (size_t)(c0 + col) * 64 + v8 * 8) = pk.u;
            }
            __syncthreads();
        }
    }
}

// =================== bf16-split GEMM (modes 0/1) =============================
#define BUF_BYTES 34816
#define GEMM_SMEM (2 * BUF_BYTES)

template <int MODE>
__global__ void __launch_bounds__(256, 2)
bf16_gemm(const float* __restrict__ A,
          const unsigned short* __restrict__ Bh,
          const unsigned short* __restrict__ Bl, int ldb,
          float* __restrict__ C,
          const float* __restrict__ bias)
{
    extern __shared__ char smem[];
    const uint32_t sbase = smem_u32(smem);
    const int tid = threadIdx.x, lane = tid & 31, wid = tid >> 5;
    const int wm = wid & 1, wn = wid >> 1;
    const size_t g0 = (size_t)blockIdx.y * 2;
    const int bcol0 = blockIdx.x * 128;

    const int sm = (tid & 31) * 4;
    const int sk = tid >> 5;
    const float* Abase = A + (g0 + (size_t)(sm >> 6)) * 16384 + (sm & 63);

    const int a_k = (lane & 7) + ((lane >> 4) << 3);
    const int a_m = ((lane >> 3) & 1) << 3;
    const int b_k = (lane & 7) + (((lane >> 3) & 1) << 3);
    const int b_n = (lane >> 4) << 3;

    float acc[4][4][4];
    #pragma unroll
    for (int i = 0; i < 4; ++i)
        #pragma unroll
        for (int j = 0; j < 4; ++j)
            #pragma unroll
            for (int r = 0; r < 4; ++r) acc[i][j][r] = 0.f;

    float4 areg[4];

    #pragma unroll
    for (int it = 0; it < 4; ++it)
        areg[it] = *(const float4*)(Abase + (size_t)(sk + it * 8) * 64);
    #pragma unroll
    for (int it = 0; it < 4; ++it) {
        const int s = tid + (it << 8);
        const int sel = s >> 9, row = (s >> 4) & 31, seg = s & 15;
        const unsigned short* src = (sel ? Bl : Bh)
            + (size_t)row * ldb + bcol0 + seg * 8;
        CP_ASYNC16(sbase + 17408 + sel * 8704 + row * 272 + seg * 16, src);
    }
    CP_COMMIT();
    #pragma unroll
    for (int it = 0; it < 4; ++it) {
        const int k = sk + it * 8;
        const float4 v = areg[it];
        __nv_bfloat162 h01 = __floats2bfloat162_rn(v.x, v.y);
        __nv_bfloat162 h23 = __floats2bfloat162_rn(v.z, v.w);
        float2 f01 = __bfloat1622float2(h01);
        float2 f23 = __bfloat1622float2(h23);
        __nv_bfloat162 l01 = __floats2bfloat162_rn(v.x - f01.x, v.y - f01.y);
        __nv_bfloat162 l23 = __floats2bfloat162_rn(v.z - f23.x, v.w - f23.y);
        char* ph = smem + (size_t)k * 272 + sm * 2;
        *(__nv_bfloat162*)(ph)     = h01;
        *(__nv_bfloat162*)(ph + 4) = h23;
        char* pl = ph + 8704;
        *(__nv_bfloat162*)(pl)     = l01;
        *(__nv_bfloat162*)(pl + 4) = l23;
    }
    CP_WAIT0();
    __syncthreads();

    int buf = 0;
    #pragma unroll 1
    for (int ch = 0; ch < 8; ++ch) {
        const int nc0 = (ch + 1) << 5;
        if (ch < 7) {
            #pragma unroll
            for (int it = 0; it < 4; ++it)
                areg[it] = *(const float4*)(Abase + (size_t)(nc0 + sk + it * 8) * 64);
            const uint32_t nb = sbase + (buf ^ 1) * BUF_BYTES;
            #pragma unroll
            for (int it = 0; it < 4; ++it) {
                const int s = tid + (it << 8);
                const int sel = s >> 9, row = (s >> 4) & 31, seg = s & 15;
                const unsigned short* src = (sel ? Bl : Bh)
                    + (size_t)(nc0 + row) * ldb + bcol0 + seg * 8;
                CP_ASYNC16(nb + 17408 + sel * 8704 + row * 272 + seg * 16, src);
            }
            CP_COMMIT();
        }

        {
            const uint32_t Ab = sbase + buf * BUF_BYTES;
            const uint32_t Bb = Ab + 17408;
            #pragma unroll
            for (int s = 0; s < 2; ++s) {
                const int klo = s << 4;
                uint32_t bh[4][2], ah[4][4];
                #pragma unroll
                for (int nbj = 0; nbj < 2; ++nbj)
                    ldmx4t(bh[2 * nbj][0], bh[2 * nbj][1],
                           bh[2 * nbj + 1][0], bh[2 * nbj + 1][1],
                           Bb + ((klo + b_k) * 136 + wn * 32 + nbj * 16 + b_n) * 2);
                #pragma unroll
                for (int mi = 0; mi < 4; ++mi)
                    ldmx4t(ah[mi][0], ah[mi][1], ah[mi][2], ah[mi][3],
                           Ab + ((klo + a_k) * 136 + wm * 64 + mi * 16 + a_m) * 2);
                #pragma unroll
                for (int mi = 0; mi < 4; ++mi)
                    #pragma unroll
                    for (int nj = 0; nj < 4; ++nj)
                        mma_bf16(acc[mi][nj], ah[mi], bh[nj]);
                {
                    uint32_t al[4][4];
                    #pragma unroll
                    for (int mi = 0; mi < 4; ++mi)
                        ldmx4t(al[mi][0], al[mi][1], al[mi][2], al[mi][3],
                               Ab + 8704 + ((klo + a_k) * 136 + wm * 64 + mi * 16 + a_m) * 2);
                    #pragma unroll
                    for (int mi = 0; mi < 4; ++mi)
                        #pragma unroll
                        for (int nj = 0; nj < 4; ++nj)
                            mma_bf16(acc[mi][nj], al[mi], bh[nj]);
                }
                {
                    uint32_t bl[4][2];
                    #pragma unroll
                    for (int nbj = 0; nbj < 2; ++nbj)
                        ldmx4t(bl[2 * nbj][0], bl[2 * nbj][1],
                               bl[2 * nbj + 1][0], bl[2 * nbj + 1][1],
                               Bb + 8704 + ((klo + b_k) * 136 + wn * 32 + nbj * 16 + b_n) * 2);
                    #pragma unroll
                    for (int mi = 0; mi < 4; ++mi)
                        #pragma unroll
                        for (int nj = 0; nj < 4; ++nj)
                            mma_bf16(acc[mi][nj], ah[mi], bl[nj]);
                }
            }
        }

        if (ch < 7) {
            char* nbuf = smem + (buf ^ 1) * BUF_BYTES;
            #pragma unroll
            for (int it = 0; it < 4; ++it) {
                const int k = sk + it * 8;
                const float4 v = areg[it];
                __nv_bfloat162 h01 = __floats2bfloat162_rn(v.x, v.y);
                __nv_bfloat162 h23 = __floats2bfloat162_rn(v.z, v.w);
                float2 f01 = __bfloat1622float2(h01);
                float2 f23 = __bfloat1622float2(h23);
                __nv_bfloat162 l01 = __floats2bfloat162_rn(v.x - f01.x, v.y - f01.y);
                __nv_bfloat162 l23 = __floats2bfloat162_rn(v.z - f23.x, v.w - f23.y);
                char* ph = nbuf + (size_t)k * 272 + sm * 2;
                *(__nv_bfloat162*)(ph)     = h01;
                *(__nv_bfloat162*)(ph + 4) = h23;
                char* pl = ph + 8704;
                *(__nv_bfloat162*)(pl)     = l01;
                *(__nv_bfloat162*)(pl + 4) = l23;
            }
        }
        CP_WAIT0();
        __syncthreads();
        buf ^= 1;
    }

    const int r0 = lane >> 2;
    const int c2 = (lane & 3) * 2;
    #pragma unroll
    for (int mi = 0; mi < 4; ++mi) {
        const int mA = wm * 64 + mi * 16 + r0;
        const size_t gg = g0 + (size_t)(mA >> 6);
        const int n = mA & 63;
        #pragma unroll
        for (int nj = 0; nj < 4; ++nj) {
            const int col = bcol0 + wn * 32 + nj * 8 + c2;
            const float b0 = bias ? __ldg(bias + col)     : 0.f;
            const float b1 = bias ? __ldg(bias + col + 1) : 0.f;
            const float v00 = acc[mi][nj][0] + b0;
            const float v01 = acc[mi][nj][1] + b1;
            const float v10 = acc[mi][nj][2] + b0;
            const float v11 = acc[mi][nj][3] + b1;
            if (MODE == 0) {
                float* p = C + gg * 16384 + (size_t)col * 64 + n;
                p[0]      = v00;
                p[64]     = v01;
                p[8]      = v10;
                p[64 + 8] = v11;
            } else {
                const size_t dg0 = (gg >> 5) * 256 + (gg & 31);
                #pragma unroll
                for (int l = 0; l < 8; ++l) {
                    float* p = C + (dg0 + (size_t)l * 32) * 16384 + (size_t)col * 64 + n;
                    p[0]      = v00;
                    p[64]     = v01;
                    p[8]      = v10;
                    p[64 + 8] = v11;
                }
            }
        }
    }
}

// ---------------- attention: per (pixel, head), softmax over 8 agents -------
__global__ void __launch_bounds__(256)
attn_kernel(const float* __restrict__ qe, const __half* __restrict__ ko,
            const __half* __restrict__ vo, float* __restrict__ oe)
{
    const int ge = blockIdx.x >> 1;              // b*32 + k
    const int b  = ge >> 5;
    const int k  = ge & 31;
    const int h  = ((blockIdx.x & 1) << 2) + (threadIdx.x >> 6);
    const int n  = threadIdx.x & 63;
    const float scale = 0.1767766952966369f;     // 32^-0.5

    const float* qp = qe + ((size_t)ge * 256 + h * 32) * 64 + n;
    float q[32];
    #pragma unroll
    for (int d = 0; d < 32; ++d) q[d] = qp[d * 64];

    float logit[8];
    #pragma unroll
    for (int j = 0; j < 8; ++j) {
        const size_t go = (size_t)(b * 8 + j) * 32 + k;
        const __half* kp = ko + (go * 256 + h * 32) * 64 + n;
        float s = 0.f;
        #pragma unroll
        for (int d = 0; d < 32; ++d) s += q[d] * __half2float(kp[d * 64]);
        logit[j] = s * scale;
    }

    float m = logit[0];
    #pragma unroll
    for (int j = 1; j < 8; ++j) m = fmaxf(m, logit[j]);
    float denom = 0.f;
    #pragma unroll
    for (int j = 0; j < 8; ++j) { logit[j] = expf(logit[j] - m); denom += logit[j]; }
    const float inv = 1.f / denom;

    float o[32];
    #pragma unroll
    for (int d = 0; d < 32; ++d) o[d] = 0.f;
    #pragma unroll
    for (int j = 0; j < 8; ++j) {
        const float a = logit[j] * inv;
        const __half* vp = vo + ((size_t)(b * 8 + j) * 32 + k) * 16384 + (h * 32) * 64 + n;
        #pragma unroll
        for (int d = 0; d < 32; ++d) o[d] += a * __half2float(vp[d * 64]);
    }

    float* op = oe + ((size_t)ge * 256 + h * 32) * 64 + n;
    #pragma unroll
    for (int d = 0; d < 32; ++d) op[d * 64] = o[d];
}

// ---------------- launcher ---------------------------------------------------
extern "C" void kernel_launch(void* const* d_in, const int* in_sizes, int n_in,
                              void* d_out, int out_size)
{
    const float* ego    = (const float*)d_in[0];
    const float* oth    = (const float*)d_in[1];
    const float* Wqkv_e = (const float*)d_in[2];
    const float* Wqkv_o = (const float*)d_in[3];
    const float* Wout_e = (const float*)d_in[4];
    const float* bout_e = (const float*)d_in[5];
    const float* Wout_o = (const float*)d_in[6];
    const float* bout_o = (const float*)d_in[7];

    float* outE = (float*)d_out;
    float* outO = outE + 16384ull * 256;

    float *qe, *oe, *Co;
    __half *koh, *voh, *wkv;
    unsigned short *wq_h, *wq_l, *we_h, *we_l, *co_h, *co_l;
    cudaGetSymbolAddress((void**)&qe, g_qe);
    cudaGetSymbolAddress((void**)&oe, g_oe);
    cudaGetSymbolAddress((void**)&koh, g_koh);
    cudaGetSymbolAddress((void**)&voh, g_voh);
    cudaGetSymbolAddress((void**)&Co, g_Co);
    cudaGetSymbolAddress((void**)&wkv, g_wkv);
    cudaGetSymbolAddress((void**)&wq_h, g_wq_h); cudaGetSymbolAddress((void**)&wq_l, g_wq_l);
    cudaGetSymbolAddress((void**)&we_h, g_we_h); cudaGetSymbolAddress((void**)&we_l, g_we_l);
    cudaGetSymbolAddress((void**)&co_h, g_co_h); cudaGetSymbolAddress((void**)&co_l, g_co_l);

    static cudaStream_t sKV = nullptr;
    static cudaEvent_t evW = nullptr, evKV = nullptr;
    if (!sKV) {
        cudaStreamCreateWithFlags(&sKV, cudaStreamNonBlocking);
        cudaEventCreateWithFlags(&evW, cudaEventDisableTiming);
        cudaEventCreateWithFlags(&evKV, cudaEventDisableTiming);
        cudaFuncSetAttribute(bf16_gemm<0>, cudaFuncAttributeMaxDynamicSharedMemorySize, GEMM_SMEM);
        cudaFuncSetAttribute(bf16_gemm<1>, cudaFuncAttributeMaxDynamicSharedMemorySize, GEMM_SMEM);
        cudaFuncSetAttribute(kv_gemm_f16, cudaFuncAttributeMaxDynamicSharedMemorySize, KV_SMEM);
    }

    // ---- KV-critical weight prep first, then fork KV immediately
    wsplit_kv<<<256, 256>>>(Wqkv_o, wkv);
    cudaEventRecord(evW, 0);
    cudaStreamWaitEvent(sKV, evW, 0);
    kv_gemm_f16<<<1024, 256, KV_SMEM, sKV>>>(oth, wkv, koh, voh);
    cudaEventRecord(evKV, sKV);

    // ---- remaining weight prep + small GEMMs on default stream (overlap KV)
    compute_Co<<<256, 256>>>(Wqkv_e, Wout_o, Co);
    wsplit_rest<<<256, 256>>>(Wqkv_e, Wout_e, Co,
                              wq_h, wq_l, we_h, we_l, co_h, co_l);
    bf16_gemm<0><<<dim3(2, 128), 256, GEMM_SMEM>>>(
        ego, wq_h, wq_l, 256, qe, nullptr);
    bf16_gemm<1><<<dim3(2, 128), 256, GEMM_SMEM>>>(
        ego, co_h, co_l, 256, outO, bout_o);

    // ---- join, attention, output projection
    cudaStreamWaitEvent(0, evKV, 0);
    attn_kernel<<<512, 256>>>(qe, koh, voh, oe);
    bf16_gemm<0><<<dim3(2, 128), 256, GEMM_SMEM>>>(
        oe, we_h, we_l, 256, outE, bout_e);
}